// round 12
// baseline (speedup 1.0000x reference)
#include <cuda_runtime.h>
#include <math.h>

#define NN   4096
#define CC   256
#define E0N  65536
#define EE   (E0N + NN)     // 69632
#define KK   2048
#define NEGS 0.2f

// ---------------- scratch (device globals; no allocation allowed) ----------------
__device__ __align__(16) float g_wv[CC];   // Wq @ w1
__device__ float g_xw[NN];                 // x[n] . gat_w[C:2C]
__device__ float g_bqw;                    // bq . w1
__device__ __align__(16) int   g_deg[NN];
__device__ __align__(16) int   g_rowptr[NN + 4];
__device__ __align__(16) int   g_curs[NN];
__device__ int   g_colj[EE];
__device__ int   g_rowi[EE];
__device__ int   g_eid[EE];                // original edge id (canonical row order key)
__device__ float g_score[EE];              // normalized attention score (main CSR order)
__device__ __align__(16) float g_out[NN * CC];
__device__ float g_A1[NN], g_B2[NN], g_C3[NN];
__device__ float g_fit[NN];
__device__ int   g_perm[KK];
__device__ float g_fitk[KK];
__device__ int   g_nidx[NN];
__device__ __align__(16) int   g_sdeg[NN];
__device__ __align__(16) int   g_srow[NN + 4];
__device__ __align__(16) int   g_scurs[NN];
__device__ int   g_scol[EE];
__device__ float g_sval[EE];

// ---------------- helpers ----------------
__device__ __forceinline__ float wsum(float v) {
    #pragma unroll
    for (int o = 16; o > 0; o >>= 1) v += __shfl_xor_sync(0xffffffffu, v, o);
    return v;
}
__device__ __forceinline__ float wmax(float v) {
    #pragma unroll
    for (int o = 16; o > 0; o >>= 1) v = fmaxf(v, __shfl_xor_sync(0xffffffffu, v, o));
    return v;
}

// warp-collective bitonic sort of 64 keys; lane holds indices (lane) and (lane+32)
__device__ __forceinline__ void bitonic64(unsigned long long& v0, unsigned long long& v1, int lane) {
    #pragma unroll
    for (int kk = 2; kk <= 64; kk <<= 1) {
        #pragma unroll
        for (int jj = kk >> 1; jj > 0; jj >>= 1) {
            if (jj == 32) {
                bool up = ((lane & kk) == 0);
                unsigned long long lo = v0 < v1 ? v0 : v1;
                unsigned long long hi = v0 < v1 ? v1 : v0;
                v0 = up ? lo : hi;
                v1 = up ? hi : lo;
            } else {
                {
                    int e = lane;
                    unsigned long long o = __shfl_xor_sync(0xffffffffu, v0, jj);
                    bool keep_min = (((e & kk) == 0) == ((e & jj) == 0));
                    v0 = keep_min ? (v0 < o ? v0 : o) : (v0 > o ? v0 : o);
                }
                {
                    int e = lane | 32;
                    unsigned long long o = __shfl_xor_sync(0xffffffffu, v1, jj);
                    bool keep_min = (((e & kk) == 0) == ((e & jj) == 0));
                    v1 = keep_min ? (v1 < o ? v1 : o) : (v1 > o ? v1 : o);
                }
            }
        }
    }
}

// ---------------- kernels ----------------

// role-split: blocks [0,512): warp-per-node xw dot; block 512: wv=Wq@w1, bqw;
// blocks >512: edge degree count.
#define XWB (NN / 8)
__global__ void k_prep(const float* x, const float* gat_w, const float* Wq,
                       const float* bq, const int* ei) {
    int b = blockIdx.x, t = threadIdx.x;
    if (b < XWB) {
        int warp = t >> 5, lane = t & 31;
        int n = b * 8 + warp;
        const float4* xr = (const float4*)(x + (size_t)n * CC);
        const float4* gw = (const float4*)(gat_w + CC);
        float s = 0.0f;
        #pragma unroll
        for (int c = 0; c < 2; c++) {
            float4 a = xr[lane + c * 32], w = gw[lane + c * 32];
            s += a.x * w.x + a.y * w.y + a.z * w.z + a.w * w.w;
        }
        s = wsum(s);
        if (lane == 0) g_xw[n] = s;
    } else if (b == XWB) {
        float s = 0.0f;
        for (int k = 0; k < CC; k++) s += Wq[t * CC + k] * gat_w[k];
        g_wv[t] = s;
        if (t == 0) {
            float bb = 0.0f;
            for (int k = 0; k < CC; k++) bb += bq[k] * gat_w[k];
            g_bqw = bb;
        }
    } else {
        int e = (b - XWB - 1) * 256 + t;
        if (e < EE) {
            int i = (e < E0N) ? ei[e] : (e - E0N);
            atomicAdd(&g_deg[i], 1);
        }
    }
}

// exclusive scan of 4096 ints, two-level warp-shuffle, one 1024-thread block.
// Self-zeroes the degree array after reading (replaces memset nodes; device
// globals start zeroed, and this maintains the invariant for the next call).
__global__ void scan4096(int which) {
    int* degm      = which ? g_sdeg : g_deg;
    int* rowptr    = which ? g_srow : g_rowptr;
    int* curs      = which ? g_scurs : g_curs;
    int t = threadIdx.x, lane = t & 31, wid = t >> 5;
    int4 d = ((const int4*)degm)[t];
    ((int4*)degm)[t] = make_int4(0, 0, 0, 0);   // reset for next call
    int tot = d.x + d.y + d.z + d.w;
    int v = tot;
    #pragma unroll
    for (int o = 1; o < 32; o <<= 1) {
        int nv = __shfl_up_sync(0xffffffffu, v, o);
        if (lane >= o) v += nv;
    }
    __shared__ int ws[32];
    if (lane == 31) ws[wid] = v;
    __syncthreads();
    if (wid == 0) {
        int s = ws[lane];
        #pragma unroll
        for (int o = 1; o < 32; o <<= 1) {
            int nv = __shfl_up_sync(0xffffffffu, s, o);
            if (lane >= o) s += nv;
        }
        ws[lane] = s;
    }
    __syncthreads();
    int base = v - tot + (wid ? ws[wid - 1] : 0);
    int p0 = base, p1 = p0 + d.x, p2 = p1 + d.y, p3 = p2 + d.z;
    ((int4*)rowptr)[t] = make_int4(p0, p1, p2, p3);
    ((int4*)curs)[t]   = make_int4(p0, p1, p2, p3);
    if (t == 1023) rowptr[4096] = ws[31];
}

__global__ void scatter_kernel(const int* ei) {
    int e = blockIdx.x * blockDim.x + threadIdx.x;
    if (e >= EE) return;
    int i, j;
    if (e < E0N) { i = ei[e]; j = ei[E0N + e]; }
    else         { i = e - E0N; j = i; }
    int p = atomicAdd(&g_curs[i], 1);
    g_colj[p] = j;
    g_rowi[p] = i;
    g_eid[p] = e;
}

// fused per-node attention + softmax + aggregation + LEConv dots.
// 4 nodes per 256-thread block; 64 threads per node; float4 per thread.
// Rows canonicalized by original edge id -> all downstream FP bit-deterministic.
__global__ void attn_out(const float4* x4, const float* gat_b,
                         const float4* le1_4, const float* le1_b,
                         const float4* le2_4, const float4* le3_4) {
    int t = threadIdx.x;
    int g = t >> 6;            // node group within block
    int q = t & 63;            // float4 slot within row
    int warp = t >> 5, lane = t & 31;
    int n = blockIdx.x * 4 + g;
    __shared__ float red[8];

    // ---- canonical row order: even warps sort their node's row by eid ----
    if ((warp & 1) == 0) {
        int rn = blockIdx.x * 4 + (warp >> 1);
        int b0 = g_rowptr[rn], blen = g_rowptr[rn + 1] - b0;
        if (blen <= 64) {
            unsigned long long v0 = (lane < blen)
                ? ((((unsigned long long)(unsigned)g_eid[b0 + lane]) << 32) | (unsigned)g_colj[b0 + lane])
                : ~0ull;
            unsigned long long v1 = (lane + 32 < blen)
                ? ((((unsigned long long)(unsigned)g_eid[b0 + lane + 32]) << 32) | (unsigned)g_colj[b0 + lane + 32])
                : ~0ull;
            bitonic64(v0, v1, lane);
            if (lane < blen)      g_colj[b0 + lane]      = (int)(v0 & 0xffffffffu);
            if (lane + 32 < blen) g_colj[b0 + lane + 32] = (int)(v1 & 0xffffffffu);
        } else if (lane == 0) {
            // practically unreachable fallback (degree > 64): serial insertion sort
            for (int a = 1; a < blen; a++) {
                int ke = g_eid[b0 + a], kc = g_colj[b0 + a];
                int bb = a - 1;
                while (bb >= 0 && g_eid[b0 + bb] > ke) {
                    g_eid[b0 + bb + 1] = g_eid[b0 + bb];
                    g_colj[b0 + bb + 1] = g_colj[b0 + bb];
                    bb--;
                }
                g_eid[b0 + bb + 1] = ke;
                g_colj[b0 + bb + 1] = kc;
            }
        }
    }
    __syncthreads();

    int s0 = g_rowptr[n], s1 = g_rowptr[n + 1];
    const float4* wv4 = (const float4*)g_wv;

    // pass 1: channelwise max over neighbors (order-independent)
    float4 mx = make_float4(-3.402823466e38f, -3.402823466e38f,
                            -3.402823466e38f, -3.402823466e38f);
    for (int p = s0; p < s1; p++) {
        float4 v = x4[(size_t)g_colj[p] * 64 + q];
        mx.x = fmaxf(mx.x, v.x); mx.y = fmaxf(mx.y, v.y);
        mx.z = fmaxf(mx.z, v.z); mx.w = fmaxf(mx.w, v.w);
    }
    float4 w = wv4[q];
    float part = mx.x * w.x + mx.y * w.y + mx.z * w.z + mx.w * w.w;
    part = wsum(part);
    if (lane == 0) red[warp] = part;
    __syncthreads();
    float mqw = red[g * 2] + red[g * 2 + 1] + g_bqw;
    __syncthreads();
    float gb = gat_b[0];

    // scores + leaky relu (elementwise, deterministic)
    float mloc = -3.402823466e38f;
    for (int p = s0 + q; p < s1; p += 64) {
        float sc = mqw + g_xw[g_colj[p]] + gb;
        sc = (sc > 0.0f) ? sc : NEGS * sc;
        g_score[p] = sc;
        mloc = fmaxf(mloc, sc);
    }
    mloc = wmax(mloc);
    if (lane == 0) red[warp] = mloc;
    __syncthreads();
    float m = fmaxf(red[g * 2], red[g * 2 + 1]);
    __syncthreads();
    // exp (elementwise)
    for (int p = s0 + q; p < s1; p += 64) g_score[p] = expf(g_score[p] - m);
    __syncthreads();
    // z: sequential sum in canonical (eid) order — matches reference accumulation
    if (q == 0) {
        float z = 0.0f;
        for (int p = s0; p < s1; p++) z += g_score[p];
        red[g * 2] = z;
    }
    __syncthreads();
    float z = red[g * 2];
    __syncthreads();
    for (int p = s0 + q; p < s1; p += 64) g_score[p] = g_score[p] / z;
    __syncthreads();   // normalized scores visible group-wide

    // pass 2: weighted aggregation (serial in canonical order)
    float4 acc = make_float4(0.f, 0.f, 0.f, 0.f);
    for (int p = s0; p < s1; p++) {
        float s = g_score[p];
        float4 v = x4[(size_t)g_colj[p] * 64 + q];
        acc.x += s * v.x; acc.y += s * v.y; acc.z += s * v.z; acc.w += s * v.w;
    }
    ((float4*)g_out)[(size_t)n * 64 + q] = acc;

    // LEConv dots
    float4 l1 = le1_4[q];
    float d1 = wsum(acc.x * l1.x + acc.y * l1.y + acc.z * l1.z + acc.w * l1.w);
    if (lane == 0) red[warp] = d1;
    __syncthreads();
    if (q == 0) g_A1[n] = red[g * 2] + red[g * 2 + 1] + le1_b[0];
    __syncthreads();
    float4 l2 = le2_4[q];
    float d2 = wsum(acc.x * l2.x + acc.y * l2.y + acc.z * l2.z + acc.w * l2.w);
    if (lane == 0) red[warp] = d2;
    __syncthreads();
    if (q == 0) g_B2[n] = red[g * 2] + red[g * 2 + 1];
    __syncthreads();
    float4 l3 = le3_4[q];
    float d3 = wsum(acc.x * l3.x + acc.y * l3.y + acc.z * l3.z + acc.w * l3.w);
    if (lane == 0) red[warp] = d3;
    __syncthreads();
    if (q == 0) g_C3[n] = red[g * 2] + red[g * 2 + 1];
}

// fused: fitness (same FP order as the standalone fit_kernel) + full bitonic
// sort of 4096 keys (fitness desc, index asc) in one block; jj<=16 in registers.
__global__ void sortfit(const float* le3_b, float* o_p) {
    __shared__ unsigned long long sk[NN];
    int t = threadIdx.x;
    float l3b = le3_b[0];
    unsigned long long v[4];
    #pragma unroll
    for (int r = 0; r < 4; r++) {
        int n = t + (r << 10);
        int s0 = g_rowptr[n], s1 = g_rowptr[n + 1];
        float s = 0.0f;
        for (int p = s0; p < s1; p++) s += g_A1[g_colj[p]];
        float agg = s - (float)(s1 - s0) * g_B2[n];
        float fv = agg + g_C3[n] + l3b;
        float fit = 1.0f / (1.0f + expf(-fv));
        g_fit[n] = fit;
        unsigned u = __float_as_uint(fit);
        u = (u & 0x80000000u) ? ~u : (u | 0x80000000u);
        v[r] = (((unsigned long long)(~u)) << 32) | (unsigned)n;
    }
    #pragma unroll
    for (int kk = 2; kk <= 32; kk <<= 1) {
        #pragma unroll
        for (int jj = kk >> 1; jj > 0; jj >>= 1) {
            #pragma unroll
            for (int r = 0; r < 4; r++) {
                int e = t | (r << 10);
                unsigned long long o = __shfl_xor_sync(0xffffffffu, v[r], jj);
                bool keep_min = (((e & kk) == 0) == ((e & jj) == 0));
                v[r] = keep_min ? (v[r] < o ? v[r] : o) : (v[r] > o ? v[r] : o);
            }
        }
    }
    #pragma unroll
    for (int r = 0; r < 4; r++) sk[t + (r << 10)] = v[r];
    __syncthreads();

    for (int kk = 64; kk <= NN; kk <<= 1) {
        for (int jj = kk >> 1; jj >= 32; jj >>= 1) {
            #pragma unroll
            for (int r = 0; r < 4; r++) {
                int i = t + (r << 10);
                int ixj = i ^ jj;
                if (ixj > i) {
                    unsigned long long a = sk[i], b = sk[ixj];
                    bool up = ((i & kk) == 0);
                    if (up ? (a > b) : (a < b)) { sk[i] = b; sk[ixj] = a; }
                }
            }
            __syncthreads();
        }
        #pragma unroll
        for (int r = 0; r < 4; r++) v[r] = sk[t + (r << 10)];
        #pragma unroll
        for (int jj = 16; jj > 0; jj >>= 1) {
            #pragma unroll
            for (int r = 0; r < 4; r++) {
                int e = t | (r << 10);
                unsigned long long o = __shfl_xor_sync(0xffffffffu, v[r], jj);
                bool keep_min = (((e & kk) == 0) == ((e & jj) == 0));
                v[r] = keep_min ? (v[r] < o ? v[r] : o) : (v[r] > o ? v[r] : o);
            }
        }
        #pragma unroll
        for (int r = 0; r < 4; r++) sk[t + (r << 10)] = v[r];
        __syncthreads();
    }

    for (int idx = t; idx < NN; idx += 1024) {
        int p = (int)(sk[idx] & 0xffffffffu);
        g_nidx[p] = (idx < KK) ? idx : -1;
        if (idx < KK) {
            g_perm[idx] = p;
            g_fitk[idx] = g_fit[p];
            o_p[idx] = (float)p;
        }
    }
}

__global__ void scount_kernel() {
    int p = blockIdx.x * blockDim.x + threadIdx.x;
    if (p >= EE) return;
    if (g_nidx[g_rowi[p]] >= 0) atomicAdd(&g_sdeg[g_colj[p]], 1);
}

__global__ void sscatter_kernel() {
    int p = blockIdx.x * blockDim.x + threadIdx.x;
    if (p >= EE) return;
    int k1 = g_nidx[g_rowi[p]];
    if (k1 >= 0) {
        int q = atomicAdd(&g_scurs[g_colj[p]], 1);
        g_scol[q] = k1;
        g_sval[q] = g_score[p];
    }
}

// Eadj = sum over edges of outer(S_row[i], S_row[j]); one WARP per edge,
// lanes flattened over the na x nb product space.
__global__ void eadj_kernel(float* o_e) {
    int w = (blockIdx.x * blockDim.x + threadIdx.x) >> 5;
    int lane = threadIdx.x & 31;
    if (w >= EE) return;
    int i = g_rowi[w], j = g_colj[w];
    int a0 = g_srow[i], na = g_srow[i + 1] - a0;
    int b0 = g_srow[j], nb = g_srow[j + 1] - b0;
    int tot = na * nb;
    for (int tix = lane; tix < tot; tix += 32) {
        int a = a0 + tix / nb;
        int b = b0 + tix % nb;
        atomicAdd(&o_e[g_scol[a] * KK + g_scol[b]], g_sval[a] * g_sval[b]);
    }
}

// fused: x_out rows + diagonal overwrite (post-eadj)
__global__ void xout_diag(float* o_x, float* o_e) {
    int k = blockIdx.x, c = threadIdx.x;
    o_x[k * CC + c] = g_out[g_perm[k] * CC + c] * g_fitk[k];
    if (c == 0) o_e[(size_t)k * KK + k] = 1.0f;
}

// ---------------- launch ----------------
extern "C" void kernel_launch(void* const* d_in, const int* in_sizes, int n_in,
                              void* d_out, int out_size) {
    const float* x      = (const float*)d_in[0];
    const int*   ei     = (const int*)  d_in[1];
    const float* Wq     = (const float*)d_in[2];
    const float* bq     = (const float*)d_in[3];
    const float* gat_w  = (const float*)d_in[4];
    const float* gat_b  = (const float*)d_in[5];
    const float* le1_w  = (const float*)d_in[6];
    const float* le1_b  = (const float*)d_in[7];
    const float* le2_w  = (const float*)d_in[8];
    const float* le3_w  = (const float*)d_in[9];
    const float* le3_b  = (const float*)d_in[10];

    float* out = (float*)d_out;
    float* o_x = out;                                  // [K, C]
    float* o_e = out + (size_t)KK * CC;                // [K, K]
    float* o_p = out + (size_t)KK * CC + (size_t)KK * KK;  // [K] perm as float

    const int EB = (EE + 255) / 256;

    cudaMemsetAsync(o_e, 0, (size_t)KK * KK * sizeof(float));

    k_prep<<<XWB + 1 + EB, 256>>>(x, gat_w, Wq, bq, ei);
    scan4096<<<1, 1024>>>(0);
    scatter_kernel<<<EB, 256>>>(ei);
    attn_out<<<NN / 4, 256>>>((const float4*)x, gat_b,
                              (const float4*)le1_w, le1_b,
                              (const float4*)le2_w, (const float4*)le3_w);
    sortfit<<<1, 1024>>>(le3_b, o_p);
    scount_kernel<<<EB, 256>>>();
    scan4096<<<1, 1024>>>(1);
    sscatter_kernel<<<EB, 256>>>();
    eadj_kernel<<<(EE * 32 + 255) / 256, 256>>>(o_e);
    xout_diag<<<KK, CC>>>(o_x, o_e);
}

// round 13
// speedup vs baseline: 1.1426x; 1.1426x over previous
#include <cuda_runtime.h>
#include <math.h>

#define NN   4096
#define CC   256
#define E0N  65536
#define EE   (E0N + NN)     // 69632
#define KK   2048
#define NEGS 0.2f

// ---------------- scratch (device globals; no allocation allowed) ----------------
__device__ __align__(16) float g_wv[CC];   // Wq @ w1
__device__ float g_xw[NN];                 // x[n] . gat_w[C:2C]
__device__ float g_bqw;                    // bq . w1
__device__ __align__(16) int   g_deg[NN];
__device__ __align__(16) int   g_rowptr[NN + 4];
__device__ __align__(16) int   g_curs[NN];
__device__ int   g_colj[EE];
__device__ int   g_rowi[EE];
__device__ int   g_eid[EE];                // original edge id (canonical row order key)
__device__ float g_score[EE];              // normalized attention score (main CSR order)
__device__ __align__(16) float g_out[NN * CC];
__device__ float g_A1[NN], g_B2[NN], g_C3[NN];
__device__ float g_fit[NN];
__device__ int   g_perm[KK];
__device__ float g_fitk[KK];
__device__ int   g_nidx[NN];
__device__ __align__(16) int   g_sdeg[NN];
__device__ __align__(16) int   g_srow[NN + 4];
__device__ __align__(16) int   g_scurs[NN];
__device__ int   g_scol[EE];
__device__ float g_sval[EE];

// ---------------- helpers ----------------
__device__ __forceinline__ float wsum(float v) {
    #pragma unroll
    for (int o = 16; o > 0; o >>= 1) v += __shfl_xor_sync(0xffffffffu, v, o);
    return v;
}
__device__ __forceinline__ float wmax(float v) {
    #pragma unroll
    for (int o = 16; o > 0; o >>= 1) v = fmaxf(v, __shfl_xor_sync(0xffffffffu, v, o));
    return v;
}

// warp-collective bitonic sort of 64 keys; lane holds indices (lane) and (lane+32)
__device__ __forceinline__ void bitonic64(unsigned long long& v0, unsigned long long& v1, int lane) {
    #pragma unroll
    for (int kk = 2; kk <= 64; kk <<= 1) {
        #pragma unroll
        for (int jj = kk >> 1; jj > 0; jj >>= 1) {
            if (jj == 32) {
                bool up = ((lane & kk) == 0);
                unsigned long long lo = v0 < v1 ? v0 : v1;
                unsigned long long hi = v0 < v1 ? v1 : v0;
                v0 = up ? lo : hi;
                v1 = up ? hi : lo;
            } else {
                {
                    int e = lane;
                    unsigned long long o = __shfl_xor_sync(0xffffffffu, v0, jj);
                    bool keep_min = (((e & kk) == 0) == ((e & jj) == 0));
                    v0 = keep_min ? (v0 < o ? v0 : o) : (v0 > o ? v0 : o);
                }
                {
                    int e = lane | 32;
                    unsigned long long o = __shfl_xor_sync(0xffffffffu, v1, jj);
                    bool keep_min = (((e & kk) == 0) == ((e & jj) == 0));
                    v1 = keep_min ? (v1 < o ? v1 : o) : (v1 > o ? v1 : o);
                }
            }
        }
    }
}

// ---------------- kernels ----------------

// role-split: blocks [0,512): warp-per-node xw dot; block 512: wv=Wq@w1, bqw;
// blocks >512: edge degree count.
#define XWB (NN / 8)
__global__ void k_prep(const float* x, const float* gat_w, const float* Wq,
                       const float* bq, const int* ei) {
    int b = blockIdx.x, t = threadIdx.x;
    if (b < XWB) {
        int warp = t >> 5, lane = t & 31;
        int n = b * 8 + warp;
        const float4* xr = (const float4*)(x + (size_t)n * CC);
        const float4* gw = (const float4*)(gat_w + CC);
        float s = 0.0f;
        #pragma unroll
        for (int c = 0; c < 2; c++) {
            float4 a = xr[lane + c * 32], w = gw[lane + c * 32];
            s += a.x * w.x + a.y * w.y + a.z * w.z + a.w * w.w;
        }
        s = wsum(s);
        if (lane == 0) g_xw[n] = s;
    } else if (b == XWB) {
        float s = 0.0f;
        for (int k = 0; k < CC; k++) s += Wq[t * CC + k] * gat_w[k];
        g_wv[t] = s;
        if (t == 0) {
            float bb = 0.0f;
            for (int k = 0; k < CC; k++) bb += bq[k] * gat_w[k];
            g_bqw = bb;
        }
    } else {
        int e = (b - XWB - 1) * 256 + t;
        if (e < EE) {
            int i = (e < E0N) ? ei[e] : (e - E0N);
            atomicAdd(&g_deg[i], 1);
        }
    }
}

// exclusive scan of 4096 ints, two-level warp-shuffle, one 1024-thread block.
// Self-zeroes the degree array after reading (replaces the memset nodes; device
// globals start zeroed and this maintains the invariant across calls).
__global__ void scan4096(int which) {
    int* degm      = which ? g_sdeg : g_deg;
    int* rowptr    = which ? g_srow : g_rowptr;
    int* curs      = which ? g_scurs : g_curs;
    int t = threadIdx.x, lane = t & 31, wid = t >> 5;
    int4 d = ((const int4*)degm)[t];
    ((int4*)degm)[t] = make_int4(0, 0, 0, 0);   // reset for next call
    int tot = d.x + d.y + d.z + d.w;
    int v = tot;
    #pragma unroll
    for (int o = 1; o < 32; o <<= 1) {
        int nv = __shfl_up_sync(0xffffffffu, v, o);
        if (lane >= o) v += nv;
    }
    __shared__ int ws[32];
    if (lane == 31) ws[wid] = v;
    __syncthreads();
    if (wid == 0) {
        int s = ws[lane];
        #pragma unroll
        for (int o = 1; o < 32; o <<= 1) {
            int nv = __shfl_up_sync(0xffffffffu, s, o);
            if (lane >= o) s += nv;
        }
        ws[lane] = s;
    }
    __syncthreads();
    int base = v - tot + (wid ? ws[wid - 1] : 0);
    int p0 = base, p1 = p0 + d.x, p2 = p1 + d.y, p3 = p2 + d.z;
    ((int4*)rowptr)[t] = make_int4(p0, p1, p2, p3);
    ((int4*)curs)[t]   = make_int4(p0, p1, p2, p3);
    if (t == 1023) rowptr[4096] = ws[31];
}

__global__ void scatter_kernel(const int* ei) {
    int e = blockIdx.x * blockDim.x + threadIdx.x;
    if (e >= EE) return;
    int i, j;
    if (e < E0N) { i = ei[e]; j = ei[E0N + e]; }
    else         { i = e - E0N; j = i; }
    int p = atomicAdd(&g_curs[i], 1);
    g_colj[p] = j;
    g_rowi[p] = i;
    g_eid[p] = e;
}

// fused per-node attention + softmax + aggregation + LEConv dots.
// 4 nodes per 256-thread block; 64 threads per node; float4 per thread.
// Rows canonicalized by original edge id -> all downstream FP bit-deterministic.
__global__ void attn_out(const float4* x4, const float* gat_b,
                         const float4* le1_4, const float* le1_b,
                         const float4* le2_4, const float4* le3_4) {
    int t = threadIdx.x;
    int g = t >> 6;            // node group within block
    int q = t & 63;            // float4 slot within row
    int warp = t >> 5, lane = t & 31;
    int n = blockIdx.x * 4 + g;
    __shared__ float red[8];

    // ---- canonical row order: even warps sort their node's row by eid ----
    if ((warp & 1) == 0) {
        int rn = blockIdx.x * 4 + (warp >> 1);
        int b0 = g_rowptr[rn], blen = g_rowptr[rn + 1] - b0;
        if (blen <= 64) {
            unsigned long long v0 = (lane < blen)
                ? ((((unsigned long long)(unsigned)g_eid[b0 + lane]) << 32) | (unsigned)g_colj[b0 + lane])
                : ~0ull;
            unsigned long long v1 = (lane + 32 < blen)
                ? ((((unsigned long long)(unsigned)g_eid[b0 + lane + 32]) << 32) | (unsigned)g_colj[b0 + lane + 32])
                : ~0ull;
            bitonic64(v0, v1, lane);
            if (lane < blen)      g_colj[b0 + lane]      = (int)(v0 & 0xffffffffu);
            if (lane + 32 < blen) g_colj[b0 + lane + 32] = (int)(v1 & 0xffffffffu);
        } else if (lane == 0) {
            // practically unreachable fallback (degree > 64): serial insertion sort
            for (int a = 1; a < blen; a++) {
                int ke = g_eid[b0 + a], kc = g_colj[b0 + a];
                int bb = a - 1;
                while (bb >= 0 && g_eid[b0 + bb] > ke) {
                    g_eid[b0 + bb + 1] = g_eid[b0 + bb];
                    g_colj[b0 + bb + 1] = g_colj[b0 + bb];
                    bb--;
                }
                g_eid[b0 + bb + 1] = ke;
                g_colj[b0 + bb + 1] = kc;
            }
        }
    }
    __syncthreads();

    int s0 = g_rowptr[n], s1 = g_rowptr[n + 1];
    const float4* wv4 = (const float4*)g_wv;

    // pass 1: channelwise max over neighbors (order-independent)
    float4 mx = make_float4(-3.402823466e38f, -3.402823466e38f,
                            -3.402823466e38f, -3.402823466e38f);
    for (int p = s0; p < s1; p++) {
        float4 v = x4[(size_t)g_colj[p] * 64 + q];
        mx.x = fmaxf(mx.x, v.x); mx.y = fmaxf(mx.y, v.y);
        mx.z = fmaxf(mx.z, v.z); mx.w = fmaxf(mx.w, v.w);
    }
    float4 w = wv4[q];
    float part = mx.x * w.x + mx.y * w.y + mx.z * w.z + mx.w * w.w;
    part = wsum(part);
    if (lane == 0) red[warp] = part;
    __syncthreads();
    float mqw = red[g * 2] + red[g * 2 + 1] + g_bqw;
    __syncthreads();
    float gb = gat_b[0];

    // scores + leaky relu (elementwise, deterministic)
    float mloc = -3.402823466e38f;
    for (int p = s0 + q; p < s1; p += 64) {
        float sc = mqw + g_xw[g_colj[p]] + gb;
        sc = (sc > 0.0f) ? sc : NEGS * sc;
        g_score[p] = sc;
        mloc = fmaxf(mloc, sc);
    }
    mloc = wmax(mloc);
    if (lane == 0) red[warp] = mloc;
    __syncthreads();
    float m = fmaxf(red[g * 2], red[g * 2 + 1]);
    __syncthreads();
    // exp (elementwise)
    for (int p = s0 + q; p < s1; p += 64) g_score[p] = expf(g_score[p] - m);
    __syncthreads();
    // z: sequential sum in canonical (eid) order — matches reference accumulation
    if (q == 0) {
        float z = 0.0f;
        for (int p = s0; p < s1; p++) z += g_score[p];
        red[g * 2] = z;
    }
    __syncthreads();
    float z = red[g * 2];
    __syncthreads();
    for (int p = s0 + q; p < s1; p += 64) g_score[p] = g_score[p] / z;
    __syncthreads();   // normalized scores visible group-wide

    // pass 2: weighted aggregation (serial in canonical order)
    float4 acc = make_float4(0.f, 0.f, 0.f, 0.f);
    for (int p = s0; p < s1; p++) {
        float s = g_score[p];
        float4 v = x4[(size_t)g_colj[p] * 64 + q];
        acc.x += s * v.x; acc.y += s * v.y; acc.z += s * v.z; acc.w += s * v.w;
    }
    ((float4*)g_out)[(size_t)n * 64 + q] = acc;

    // LEConv dots
    float4 l1 = le1_4[q];
    float d1 = wsum(acc.x * l1.x + acc.y * l1.y + acc.z * l1.z + acc.w * l1.w);
    if (lane == 0) red[warp] = d1;
    __syncthreads();
    if (q == 0) g_A1[n] = red[g * 2] + red[g * 2 + 1] + le1_b[0];
    __syncthreads();
    float4 l2 = le2_4[q];
    float d2 = wsum(acc.x * l2.x + acc.y * l2.y + acc.z * l2.z + acc.w * l2.w);
    if (lane == 0) red[warp] = d2;
    __syncthreads();
    if (q == 0) g_B2[n] = red[g * 2] + red[g * 2 + 1];
    __syncthreads();
    float4 l3 = le3_4[q];
    float d3 = wsum(acc.x * l3.x + acc.y * l3.y + acc.z * l3.z + acc.w * l3.w);
    if (lane == 0) red[warp] = d3;
    __syncthreads();
    if (q == 0) g_C3[n] = red[g * 2] + red[g * 2 + 1];
}

__global__ void fit_kernel(const float* le3_b) {
    int n = blockIdx.x * blockDim.x + threadIdx.x;
    if (n >= NN) return;
    int s0 = g_rowptr[n], s1 = g_rowptr[n + 1];
    float s = 0.0f;
    for (int p = s0; p < s1; p++) s += g_A1[g_colj[p]];
    float agg = s - (float)(s1 - s0) * g_B2[n];
    float v = agg + g_C3[n] + le3_b[0];
    g_fit[n] = 1.0f / (1.0f + expf(-v));
}

// full bitonic sort of 4096 (fitness desc, index asc) in one block.
// Phases with jj<=16 run in registers with warp shuffles.
__global__ void sort_kernel(float* o_p) {
    __shared__ unsigned long long sk[NN];
    int t = threadIdx.x;
    unsigned long long v[4];
    #pragma unroll
    for (int r = 0; r < 4; r++) {
        int n = t + (r << 10);
        unsigned u = __float_as_uint(g_fit[n]);
        u = (u & 0x80000000u) ? ~u : (u | 0x80000000u);
        v[r] = (((unsigned long long)(~u)) << 32) | (unsigned)n;
    }
    #pragma unroll
    for (int kk = 2; kk <= 32; kk <<= 1) {
        #pragma unroll
        for (int jj = kk >> 1; jj > 0; jj >>= 1) {
            #pragma unroll
            for (int r = 0; r < 4; r++) {
                int e = t | (r << 10);
                unsigned long long o = __shfl_xor_sync(0xffffffffu, v[r], jj);
                bool keep_min = (((e & kk) == 0) == ((e & jj) == 0));
                v[r] = keep_min ? (v[r] < o ? v[r] : o) : (v[r] > o ? v[r] : o);
            }
        }
    }
    #pragma unroll
    for (int r = 0; r < 4; r++) sk[t + (r << 10)] = v[r];
    __syncthreads();

    for (int kk = 64; kk <= NN; kk <<= 1) {
        for (int jj = kk >> 1; jj >= 32; jj >>= 1) {
            #pragma unroll
            for (int r = 0; r < 4; r++) {
                int i = t + (r << 10);
                int ixj = i ^ jj;
                if (ixj > i) {
                    unsigned long long a = sk[i], b = sk[ixj];
                    bool up = ((i & kk) == 0);
                    if (up ? (a > b) : (a < b)) { sk[i] = b; sk[ixj] = a; }
                }
            }
            __syncthreads();
        }
        #pragma unroll
        for (int r = 0; r < 4; r++) v[r] = sk[t + (r << 10)];
        #pragma unroll
        for (int jj = 16; jj > 0; jj >>= 1) {
            #pragma unroll
            for (int r = 0; r < 4; r++) {
                int e = t | (r << 10);
                unsigned long long o = __shfl_xor_sync(0xffffffffu, v[r], jj);
                bool keep_min = (((e & kk) == 0) == ((e & jj) == 0));
                v[r] = keep_min ? (v[r] < o ? v[r] : o) : (v[r] > o ? v[r] : o);
            }
        }
        #pragma unroll
        for (int r = 0; r < 4; r++) sk[t + (r << 10)] = v[r];
        __syncthreads();
    }

    for (int idx = t; idx < NN; idx += 1024) {
        int p = (int)(sk[idx] & 0xffffffffu);
        g_nidx[p] = (idx < KK) ? idx : -1;
        if (idx < KK) {
            g_perm[idx] = p;
            g_fitk[idx] = g_fit[p];
            o_p[idx] = (float)p;
        }
    }
}

__global__ void scount_kernel() {
    int p = blockIdx.x * blockDim.x + threadIdx.x;
    if (p >= EE) return;
    if (g_nidx[g_rowi[p]] >= 0) atomicAdd(&g_sdeg[g_colj[p]], 1);
}

__global__ void sscatter_kernel() {
    int p = blockIdx.x * blockDim.x + threadIdx.x;
    if (p >= EE) return;
    int k1 = g_nidx[g_rowi[p]];
    if (k1 >= 0) {
        int q = atomicAdd(&g_scurs[g_colj[p]], 1);
        g_scol[q] = k1;
        g_sval[q] = g_score[p];
    }
}

// Eadj = sum over edges of outer(S_row[i], S_row[j]); one WARP per edge,
// lanes flattened over the na x nb product space.
__global__ void eadj_kernel(float* o_e) {
    int w = (blockIdx.x * blockDim.x + threadIdx.x) >> 5;
    int lane = threadIdx.x & 31;
    if (w >= EE) return;
    int i = g_rowi[w], j = g_colj[w];
    int a0 = g_srow[i], na = g_srow[i + 1] - a0;
    int b0 = g_srow[j], nb = g_srow[j + 1] - b0;
    int tot = na * nb;
    for (int tix = lane; tix < tot; tix += 32) {
        int a = a0 + tix / nb;
        int b = b0 + tix % nb;
        atomicAdd(&o_e[g_scol[a] * KK + g_scol[b]], g_sval[a] * g_sval[b]);
    }
}

// fused: x_out rows + diagonal overwrite (post-eadj)
__global__ void xout_diag(float* o_x, float* o_e) {
    int k = blockIdx.x, c = threadIdx.x;
    o_x[k * CC + c] = g_out[g_perm[k] * CC + c] * g_fitk[k];
    if (c == 0) o_e[(size_t)k * KK + k] = 1.0f;
}

// ---------------- launch ----------------
extern "C" void kernel_launch(void* const* d_in, const int* in_sizes, int n_in,
                              void* d_out, int out_size) {
    const float* x      = (const float*)d_in[0];
    const int*   ei     = (const int*)  d_in[1];
    const float* Wq     = (const float*)d_in[2];
    const float* bq     = (const float*)d_in[3];
    const float* gat_w  = (const float*)d_in[4];
    const float* gat_b  = (const float*)d_in[5];
    const float* le1_w  = (const float*)d_in[6];
    const float* le1_b  = (const float*)d_in[7];
    const float* le2_w  = (const float*)d_in[8];
    const float* le3_w  = (const float*)d_in[9];
    const float* le3_b  = (const float*)d_in[10];

    float* out = (float*)d_out;
    float* o_x = out;                                  // [K, C]
    float* o_e = out + (size_t)KK * CC;                // [K, K]
    float* o_p = out + (size_t)KK * CC + (size_t)KK * KK;  // [K] perm as float

    const int EB = (EE + 255) / 256;

    cudaMemsetAsync(o_e, 0, (size_t)KK * KK * sizeof(float));

    k_prep<<<XWB + 1 + EB, 256>>>(x, gat_w, Wq, bq, ei);
    scan4096<<<1, 1024>>>(0);
    scatter_kernel<<<EB, 256>>>(ei);
    attn_out<<<NN / 4, 256>>>((const float4*)x, gat_b,
                              (const float4*)le1_w, le1_b,
                              (const float4*)le2_w, (const float4*)le3_w);
    fit_kernel<<<(NN + 255) / 256, 256>>>(le3_b);
    sort_kernel<<<1, 1024>>>(o_p);
    scount_kernel<<<EB, 256>>>();
    scan4096<<<1, 1024>>>(1);
    sscatter_kernel<<<EB, 256>>>();
    eadj_kernel<<<(EE * 32 + 255) / 256, 256>>>(o_e);
    xout_diag<<<KK, CC>>>(o_x, o_e);
}

// round 14
// speedup vs baseline: 1.4503x; 1.2692x over previous
#include <cuda_runtime.h>
#include <math.h>

#define NN   4096
#define CC   256
#define E0N  65536
#define EE   (E0N + NN)     // 69632
#define KK   2048
#define NEGS 0.2f

// ---------------- scratch (device globals; no allocation allowed) ----------------
__device__ __align__(16) float g_wv[CC];   // Wq @ w1
__device__ float g_xw[NN];                 // x[n] . gat_w[C:2C]
__device__ float g_bqw;                    // bq . w1
__device__ __align__(16) int   g_deg[NN];
__device__ __align__(16) int   g_rowptr[NN + 4];
__device__ __align__(16) int   g_curs[NN];
__device__ int   g_colj[EE];
__device__ int   g_rowi[EE];
__device__ int   g_eid[EE];                // original edge id (canonical row order key)
__device__ float g_score[EE];              // normalized attention score (main CSR order)
__device__ __align__(16) float g_out[NN * CC];
__device__ float g_A1[NN], g_B2[NN], g_C3[NN];
__device__ float g_fit[NN];
__device__ int   g_perm[KK];
__device__ float g_fitk[KK];
__device__ int   g_nidx[NN];
__device__ __align__(16) int   g_sdeg[NN];
__device__ __align__(16) int   g_srow[NN + 4];
__device__ __align__(16) int   g_scurs[NN];
__device__ int   g_scol[EE];
__device__ float g_sval[EE];

// ---------------- helpers ----------------
__device__ __forceinline__ float wsum(float v) {
    #pragma unroll
    for (int o = 16; o > 0; o >>= 1) v += __shfl_xor_sync(0xffffffffu, v, o);
    return v;
}
__device__ __forceinline__ float wmax(float v) {
    #pragma unroll
    for (int o = 16; o > 0; o >>= 1) v = fmaxf(v, __shfl_xor_sync(0xffffffffu, v, o));
    return v;
}

// warp-collective bitonic sort of 64 keys; lane holds indices (lane) and (lane+32)
__device__ __forceinline__ void bitonic64(unsigned long long& v0, unsigned long long& v1, int lane) {
    #pragma unroll
    for (int kk = 2; kk <= 64; kk <<= 1) {
        #pragma unroll
        for (int jj = kk >> 1; jj > 0; jj >>= 1) {
            if (jj == 32) {
                bool up = ((lane & kk) == 0);
                unsigned long long lo = v0 < v1 ? v0 : v1;
                unsigned long long hi = v0 < v1 ? v1 : v0;
                v0 = up ? lo : hi;
                v1 = up ? hi : lo;
            } else {
                {
                    int e = lane;
                    unsigned long long o = __shfl_xor_sync(0xffffffffu, v0, jj);
                    bool keep_min = (((e & kk) == 0) == ((e & jj) == 0));
                    v0 = keep_min ? (v0 < o ? v0 : o) : (v0 > o ? v0 : o);
                }
                {
                    int e = lane | 32;
                    unsigned long long o = __shfl_xor_sync(0xffffffffu, v1, jj);
                    bool keep_min = (((e & kk) == 0) == ((e & jj) == 0));
                    v1 = keep_min ? (v1 < o ? v1 : o) : (v1 > o ? v1 : o);
                }
            }
        }
    }
}

// ---------------- kernels ----------------

// role-split:
//   blocks [0, XWB):          warp-per-node xw dot (coalesced float4)
//   blocks [XWB, XWB+WVB):    wv rows — stage 8 Wq rows to smem coalesced,
//                             then 8 threads run the EXACT serial k-loop
//                             (FP order preserved vs original)
//   block  XWB+WVB:           bqw (serial, original FP order)
//   blocks > XWB+WVB:         edge degree count
#define XWB (NN / 8)
#define WVB (CC / 8)    // 32 blocks, 8 wv rows each
__global__ void k_prep(const float* x, const float* gat_w, const float* Wq,
                       const float* bq, const int* ei) {
    int b = blockIdx.x, t = threadIdx.x;
    if (b < XWB) {
        int warp = t >> 5, lane = t & 31;
        int n = b * 8 + warp;
        const float4* xr = (const float4*)(x + (size_t)n * CC);
        const float4* gw = (const float4*)(gat_w + CC);
        float s = 0.0f;
        #pragma unroll
        for (int c = 0; c < 2; c++) {
            float4 a = xr[lane + c * 32], w = gw[lane + c * 32];
            s += a.x * w.x + a.y * w.y + a.z * w.z + a.w * w.w;
        }
        s = wsum(s);
        if (lane == 0) g_xw[n] = s;
    } else if (b < XWB + WVB) {
        __shared__ float sw[8 * CC];
        int warp = t >> 5, lane = t & 31;
        int r0 = (b - XWB) * 8;
        // coalesced copy: each warp stages one contiguous Wq row (1KB)
        const float4* src = (const float4*)(Wq + (size_t)(r0 + warp) * CC);
        float4* dst = (float4*)(sw + warp * CC);
        #pragma unroll
        for (int c = 0; c < 2; c++) dst[lane + c * 32] = src[lane + c * 32];
        __syncthreads();
        if (t < 8) {
            // exact original FP order: serial sum over k ascending
            float s = 0.0f;
            const float* row = sw + t * CC;
            for (int k = 0; k < CC; k++) s += row[k] * gat_w[k];
            g_wv[r0 + t] = s;
        }
    } else if (b == XWB + WVB) {
        if (t == 0) {
            float bb = 0.0f;
            for (int k = 0; k < CC; k++) bb += bq[k] * gat_w[k];
            g_bqw = bb;
        }
    } else {
        int e = (b - XWB - WVB - 1) * 256 + t;
        if (e < EE) {
            int i = (e < E0N) ? ei[e] : (e - E0N);
            atomicAdd(&g_deg[i], 1);
        }
    }
}

// exclusive scan of 4096 ints, two-level warp-shuffle, one 1024-thread block.
// Self-zeroes the degree array after reading (replaces the memset nodes; device
// globals start zeroed and this maintains the invariant across calls).
__global__ void scan4096(int which) {
    int* degm      = which ? g_sdeg : g_deg;
    int* rowptr    = which ? g_srow : g_rowptr;
    int* curs      = which ? g_scurs : g_curs;
    int t = threadIdx.x, lane = t & 31, wid = t >> 5;
    int4 d = ((const int4*)degm)[t];
    ((int4*)degm)[t] = make_int4(0, 0, 0, 0);   // reset for next call
    int tot = d.x + d.y + d.z + d.w;
    int v = tot;
    #pragma unroll
    for (int o = 1; o < 32; o <<= 1) {
        int nv = __shfl_up_sync(0xffffffffu, v, o);
        if (lane >= o) v += nv;
    }
    __shared__ int ws[32];
    if (lane == 31) ws[wid] = v;
    __syncthreads();
    if (wid == 0) {
        int s = ws[lane];
        #pragma unroll
        for (int o = 1; o < 32; o <<= 1) {
            int nv = __shfl_up_sync(0xffffffffu, s, o);
            if (lane >= o) s += nv;
        }
        ws[lane] = s;
    }
    __syncthreads();
    int base = v - tot + (wid ? ws[wid - 1] : 0);
    int p0 = base, p1 = p0 + d.x, p2 = p1 + d.y, p3 = p2 + d.z;
    ((int4*)rowptr)[t] = make_int4(p0, p1, p2, p3);
    ((int4*)curs)[t]   = make_int4(p0, p1, p2, p3);
    if (t == 1023) rowptr[4096] = ws[31];
}

__global__ void scatter_kernel(const int* ei) {
    int e = blockIdx.x * blockDim.x + threadIdx.x;
    if (e >= EE) return;
    int i, j;
    if (e < E0N) { i = ei[e]; j = ei[E0N + e]; }
    else         { i = e - E0N; j = i; }
    int p = atomicAdd(&g_curs[i], 1);
    g_colj[p] = j;
    g_rowi[p] = i;
    g_eid[p] = e;
}

// fused per-node attention + softmax + aggregation + LEConv dots.
// 4 nodes per 256-thread block; 64 threads per node; float4 per thread.
// Rows canonicalized by original edge id -> all downstream FP bit-deterministic.
__global__ void attn_out(const float4* x4, const float* gat_b,
                         const float4* le1_4, const float* le1_b,
                         const float4* le2_4, const float4* le3_4) {
    int t = threadIdx.x;
    int g = t >> 6;            // node group within block
    int q = t & 63;            // float4 slot within row
    int warp = t >> 5, lane = t & 31;
    int n = blockIdx.x * 4 + g;
    __shared__ float red[8];

    // ---- canonical row order: even warps sort their node's row by eid ----
    if ((warp & 1) == 0) {
        int rn = blockIdx.x * 4 + (warp >> 1);
        int b0 = g_rowptr[rn], blen = g_rowptr[rn + 1] - b0;
        if (blen <= 64) {
            unsigned long long v0 = (lane < blen)
                ? ((((unsigned long long)(unsigned)g_eid[b0 + lane]) << 32) | (unsigned)g_colj[b0 + lane])
                : ~0ull;
            unsigned long long v1 = (lane + 32 < blen)
                ? ((((unsigned long long)(unsigned)g_eid[b0 + lane + 32]) << 32) | (unsigned)g_colj[b0 + lane + 32])
                : ~0ull;
            bitonic64(v0, v1, lane);
            if (lane < blen)      g_colj[b0 + lane]      = (int)(v0 & 0xffffffffu);
            if (lane + 32 < blen) g_colj[b0 + lane + 32] = (int)(v1 & 0xffffffffu);
        } else if (lane == 0) {
            // practically unreachable fallback (degree > 64): serial insertion sort
            for (int a = 1; a < blen; a++) {
                int ke = g_eid[b0 + a], kc = g_colj[b0 + a];
                int bb = a - 1;
                while (bb >= 0 && g_eid[b0 + bb] > ke) {
                    g_eid[b0 + bb + 1] = g_eid[b0 + bb];
                    g_colj[b0 + bb + 1] = g_colj[b0 + bb];
                    bb--;
                }
                g_eid[b0 + bb + 1] = ke;
                g_colj[b0 + bb + 1] = kc;
            }
        }
    }
    __syncthreads();

    int s0 = g_rowptr[n], s1 = g_rowptr[n + 1];
    const float4* wv4 = (const float4*)g_wv;

    // pass 1: channelwise max over neighbors (order-independent)
    float4 mx = make_float4(-3.402823466e38f, -3.402823466e38f,
                            -3.402823466e38f, -3.402823466e38f);
    for (int p = s0; p < s1; p++) {
        float4 v = x4[(size_t)g_colj[p] * 64 + q];
        mx.x = fmaxf(mx.x, v.x); mx.y = fmaxf(mx.y, v.y);
        mx.z = fmaxf(mx.z, v.z); mx.w = fmaxf(mx.w, v.w);
    }
    float4 w = wv4[q];
    float part = mx.x * w.x + mx.y * w.y + mx.z * w.z + mx.w * w.w;
    part = wsum(part);
    if (lane == 0) red[warp] = part;
    __syncthreads();
    float mqw = red[g * 2] + red[g * 2 + 1] + g_bqw;
    __syncthreads();
    float gb = gat_b[0];

    // scores + leaky relu (elementwise, deterministic)
    float mloc = -3.402823466e38f;
    for (int p = s0 + q; p < s1; p += 64) {
        float sc = mqw + g_xw[g_colj[p]] + gb;
        sc = (sc > 0.0f) ? sc : NEGS * sc;
        g_score[p] = sc;
        mloc = fmaxf(mloc, sc);
    }
    mloc = wmax(mloc);
    if (lane == 0) red[warp] = mloc;
    __syncthreads();
    float m = fmaxf(red[g * 2], red[g * 2 + 1]);
    __syncthreads();
    // exp (elementwise)
    for (int p = s0 + q; p < s1; p += 64) g_score[p] = expf(g_score[p] - m);
    __syncthreads();
    // z: sequential sum in canonical (eid) order — matches reference accumulation
    if (q == 0) {
        float z = 0.0f;
        for (int p = s0; p < s1; p++) z += g_score[p];
        red[g * 2] = z;
    }
    __syncthreads();
    float z = red[g * 2];
    __syncthreads();
    for (int p = s0 + q; p < s1; p += 64) g_score[p] = g_score[p] / z;
    __syncthreads();   // normalized scores visible group-wide

    // pass 2: weighted aggregation (serial in canonical order)
    float4 acc = make_float4(0.f, 0.f, 0.f, 0.f);
    for (int p = s0; p < s1; p++) {
        float s = g_score[p];
        float4 v = x4[(size_t)g_colj[p] * 64 + q];
        acc.x += s * v.x; acc.y += s * v.y; acc.z += s * v.z; acc.w += s * v.w;
    }
    ((float4*)g_out)[(size_t)n * 64 + q] = acc;

    // LEConv dots
    float4 l1 = le1_4[q];
    float d1 = wsum(acc.x * l1.x + acc.y * l1.y + acc.z * l1.z + acc.w * l1.w);
    if (lane == 0) red[warp] = d1;
    __syncthreads();
    if (q == 0) g_A1[n] = red[g * 2] + red[g * 2 + 1] + le1_b[0];
    __syncthreads();
    float4 l2 = le2_4[q];
    float d2 = wsum(acc.x * l2.x + acc.y * l2.y + acc.z * l2.z + acc.w * l2.w);
    if (lane == 0) red[warp] = d2;
    __syncthreads();
    if (q == 0) g_B2[n] = red[g * 2] + red[g * 2 + 1];
    __syncthreads();
    float4 l3 = le3_4[q];
    float d3 = wsum(acc.x * l3.x + acc.y * l3.y + acc.z * l3.z + acc.w * l3.w);
    if (lane == 0) red[warp] = d3;
    __syncthreads();
    if (q == 0) g_C3[n] = red[g * 2] + red[g * 2 + 1];
}

__global__ void fit_kernel(const float* le3_b) {
    int n = blockIdx.x * blockDim.x + threadIdx.x;
    if (n >= NN) return;
    int s0 = g_rowptr[n], s1 = g_rowptr[n + 1];
    float s = 0.0f;
    for (int p = s0; p < s1; p++) s += g_A1[g_colj[p]];
    float agg = s - (float)(s1 - s0) * g_B2[n];
    float v = agg + g_C3[n] + le3_b[0];
    g_fit[n] = 1.0f / (1.0f + expf(-v));
}

// full bitonic sort of 4096 (fitness desc, index asc) in one block.
// Phases with jj<=16 run in registers with warp shuffles.
__global__ void sort_kernel(float* o_p) {
    __shared__ unsigned long long sk[NN];
    int t = threadIdx.x;
    unsigned long long v[4];
    #pragma unroll
    for (int r = 0; r < 4; r++) {
        int n = t + (r << 10);
        unsigned u = __float_as_uint(g_fit[n]);
        u = (u & 0x80000000u) ? ~u : (u | 0x80000000u);
        v[r] = (((unsigned long long)(~u)) << 32) | (unsigned)n;
    }
    #pragma unroll
    for (int kk = 2; kk <= 32; kk <<= 1) {
        #pragma unroll
        for (int jj = kk >> 1; jj > 0; jj >>= 1) {
            #pragma unroll
            for (int r = 0; r < 4; r++) {
                int e = t | (r << 10);
                unsigned long long o = __shfl_xor_sync(0xffffffffu, v[r], jj);
                bool keep_min = (((e & kk) == 0) == ((e & jj) == 0));
                v[r] = keep_min ? (v[r] < o ? v[r] : o) : (v[r] > o ? v[r] : o);
            }
        }
    }
    #pragma unroll
    for (int r = 0; r < 4; r++) sk[t + (r << 10)] = v[r];
    __syncthreads();

    for (int kk = 64; kk <= NN; kk <<= 1) {
        for (int jj = kk >> 1; jj >= 32; jj >>= 1) {
            #pragma unroll
            for (int r = 0; r < 4; r++) {
                int i = t + (r << 10);
                int ixj = i ^ jj;
                if (ixj > i) {
                    unsigned long long a = sk[i], b = sk[ixj];
                    bool up = ((i & kk) == 0);
                    if (up ? (a > b) : (a < b)) { sk[i] = b; sk[ixj] = a; }
                }
            }
            __syncthreads();
        }
        #pragma unroll
        for (int r = 0; r < 4; r++) v[r] = sk[t + (r << 10)];
        #pragma unroll
        for (int jj = 16; jj > 0; jj >>= 1) {
            #pragma unroll
            for (int r = 0; r < 4; r++) {
                int e = t | (r << 10);
                unsigned long long o = __shfl_xor_sync(0xffffffffu, v[r], jj);
                bool keep_min = (((e & kk) == 0) == ((e & jj) == 0));
                v[r] = keep_min ? (v[r] < o ? v[r] : o) : (v[r] > o ? v[r] : o);
            }
        }
        #pragma unroll
        for (int r = 0; r < 4; r++) sk[t + (r << 10)] = v[r];
        __syncthreads();
    }

    for (int idx = t; idx < NN; idx += 1024) {
        int p = (int)(sk[idx] & 0xffffffffu);
        g_nidx[p] = (idx < KK) ? idx : -1;
        if (idx < KK) {
            g_perm[idx] = p;
            g_fitk[idx] = g_fit[p];
            o_p[idx] = (float)p;
        }
    }
}

__global__ void scount_kernel() {
    int p = blockIdx.x * blockDim.x + threadIdx.x;
    if (p >= EE) return;
    if (g_nidx[g_rowi[p]] >= 0) atomicAdd(&g_sdeg[g_colj[p]], 1);
}

__global__ void sscatter_kernel() {
    int p = blockIdx.x * blockDim.x + threadIdx.x;
    if (p >= EE) return;
    int k1 = g_nidx[g_rowi[p]];
    if (k1 >= 0) {
        int q = atomicAdd(&g_scurs[g_colj[p]], 1);
        g_scol[q] = k1;
        g_sval[q] = g_score[p];
    }
}

// Eadj = sum over edges of outer(S_row[i], S_row[j]); one WARP per edge,
// lanes flattened over the na x nb product space.
__global__ void eadj_kernel(float* o_e) {
    int w = (blockIdx.x * blockDim.x + threadIdx.x) >> 5;
    int lane = threadIdx.x & 31;
    if (w >= EE) return;
    int i = g_rowi[w], j = g_colj[w];
    int a0 = g_srow[i], na = g_srow[i + 1] - a0;
    int b0 = g_srow[j], nb = g_srow[j + 1] - b0;
    int tot = na * nb;
    for (int tix = lane; tix < tot; tix += 32) {
        int a = a0 + tix / nb;
        int b = b0 + tix % nb;
        atomicAdd(&o_e[g_scol[a] * KK + g_scol[b]], g_sval[a] * g_sval[b]);
    }
}

// fused: x_out rows + diagonal overwrite (post-eadj)
__global__ void xout_diag(float* o_x, float* o_e) {
    int k = blockIdx.x, c = threadIdx.x;
    o_x[k * CC + c] = g_out[g_perm[k] * CC + c] * g_fitk[k];
    if (c == 0) o_e[(size_t)k * KK + k] = 1.0f;
}

// ---------------- launch ----------------
extern "C" void kernel_launch(void* const* d_in, const int* in_sizes, int n_in,
                              void* d_out, int out_size) {
    const float* x      = (const float*)d_in[0];
    const int*   ei     = (const int*)  d_in[1];
    const float* Wq     = (const float*)d_in[2];
    const float* bq     = (const float*)d_in[3];
    const float* gat_w  = (const float*)d_in[4];
    const float* gat_b  = (const float*)d_in[5];
    const float* le1_w  = (const float*)d_in[6];
    const float* le1_b  = (const float*)d_in[7];
    const float* le2_w  = (const float*)d_in[8];
    const float* le3_w  = (const float*)d_in[9];
    const float* le3_b  = (const float*)d_in[10];

    float* out = (float*)d_out;
    float* o_x = out;                                  // [K, C]
    float* o_e = out + (size_t)KK * CC;                // [K, K]
    float* o_p = out + (size_t)KK * CC + (size_t)KK * KK;  // [K] perm as float

    const int EB = (EE + 255) / 256;

    cudaMemsetAsync(o_e, 0, (size_t)KK * KK * sizeof(float));

    k_prep<<<XWB + WVB + 1 + EB, 256>>>(x, gat_w, Wq, bq, ei);
    scan4096<<<1, 1024>>>(0);
    scatter_kernel<<<EB, 256>>>(ei);
    attn_out<<<NN / 4, 256>>>((const float4*)x, gat_b,
                              (const float4*)le1_w, le1_b,
                              (const float4*)le2_w, (const float4*)le3_w);
    fit_kernel<<<(NN + 255) / 256, 256>>>(le3_b);
    sort_kernel<<<1, 1024>>>(o_p);
    scount_kernel<<<EB, 256>>>();
    scan4096<<<1, 1024>>>(1);
    sscatter_kernel<<<EB, 256>>>();
    eadj_kernel<<<(EE * 32 + 255) / 256, 256>>>(o_e);
    xout_diag<<<KK, CC>>>(o_x, o_e);
}